// round 4
// baseline (speedup 1.0000x reference)
#include <cuda_runtime.h>

// Problem constants
#define NB_UP    8      // electrons per spin channel
#define NMO_     40     // molecular orbitals
#define NELEC_   16     // total electrons (2 * NB_UP)
#define COL_STRIDE 12   // floats per stored column (48 B), conflict-friendly stride
#define NCONF_   256

// One block per walker; 512 threads: thread (s, c) with s = t>>8, c = t&255
// computes ONE 8x8 Slater determinant (spin s, config c). Halving per-thread
// live state vs the 2-det version keeps the LU matrix fully register-resident
// (no local-memory spills, which bound the previous versions).
__global__ __launch_bounds__(2 * NCONF_, 1)
void slater_det_kernel(const float* __restrict__ mo,
                       const int*   __restrict__ cup,
                       const int*   __restrict__ cdown,
                       float*       __restrict__ out,
                       int nconf)
{
    __shared__ float mo_T[2 * NMO_ * COL_STRIDE];   // 960 floats = 3840 B
    __shared__ float sh_dn[NCONF_];                 // down-spin dets, 1 KB

    const int b = blockIdx.x;
    const int t = threadIdx.x;

    // Stage + transpose this walker's MO block (16x40 f32, 640 elements).
    // mo_T[(s*NMO_+col)*COL_STRIDE + i] = mo[b, s*8+i, col]
    {
        const float* src = mo + (size_t)b * (NELEC_ * NMO_);
        #pragma unroll
        for (int idx = t; idx < NELEC_ * NMO_; idx += 2 * NCONF_) {
            const int i   = idx / NMO_;     // electron row 0..15
            const int col = idx % NMO_;     // MO column 0..39
            mo_T[((i >> 3) * NMO_ + col) * COL_STRIDE + (i & 7)] = src[idx];
        }
    }
    __syncthreads();

    const int s = t >> 8;          // spin channel (warp-uniform)
    const int c = t & (NCONF_ - 1);

    float det = 1.0f;

    if (c < nconf) {
        const int*   cw      = ((s == 0) ? cup : cdown) + c * NB_UP;
        const float* colbase = mo_T + s * NMO_ * COL_STRIDE;

        // Vectorized index load: 8 ints = 2x int4 (row base is 32B-aligned).
        const int4 ci0 = __ldg((const int4*)cw);
        const int4 ci1 = __ldg((const int4*)cw + 1);
        const int cols[NB_UP] = {ci0.x, ci0.y, ci0.z, ci0.w, ci1.x, ci1.y, ci1.z, ci1.w};

        // Gather the 8x8 Slater matrix: column j contiguous -> two LDS.128.
        float a[NB_UP][NB_UP];
        #pragma unroll
        for (int j = 0; j < NB_UP; ++j) {
            const float4* p = reinterpret_cast<const float4*>(colbase + cols[j] * COL_STRIDE);
            const float4 lo = p[0];
            const float4 hi = p[1];
            a[0][j] = lo.x; a[1][j] = lo.y; a[2][j] = lo.z; a[3][j] = lo.w;
            a[4][j] = hi.x; a[5][j] = hi.y; a[6][j] = hi.z; a[7][j] = hi.w;
        }

        // Fully-unrolled in-register LU with partial pivoting
        // (predicated bubble-max swaps; sign tracked via select).
        #pragma unroll
        for (int k = 0; k < NB_UP; ++k) {
            #pragma unroll
            for (int r = k + 1; r < NB_UP; ++r) {
                const bool sw = fabsf(a[r][k]) > fabsf(a[k][k]);
                det = sw ? -det : det;
                #pragma unroll
                for (int j = k; j < NB_UP; ++j) {
                    const float t0 = a[k][j];
                    const float t1 = a[r][j];
                    a[k][j] = sw ? t1 : t0;
                    a[r][j] = sw ? t0 : t1;
                }
            }
            const float piv = a[k][k];
            det *= piv;
            const float inv = __frcp_rn(piv);
            #pragma unroll
            for (int r = k + 1; r < NB_UP; ++r) {
                const float f = a[r][k] * inv;
                #pragma unroll
                for (int j = k + 1; j < NB_UP; ++j)
                    a[r][j] = fmaf(-f, a[k][j], a[r][j]);
            }
        }
    }

    // Combine spins: down-threads publish, up-threads multiply and store.
    if (s == 1) sh_dn[c] = det;
    __syncthreads();
    if (s == 0 && c < nconf)
        out[(size_t)b * nconf + c] = det * sh_dn[c];
}

extern "C" void kernel_launch(void* const* d_in, const int* in_sizes, int n_in,
                              void* d_out, int out_size)
{
    const float* mo    = (const float*)d_in[0];  // (B, 16, 40) f32
    const int*   cup   = (const int*)  d_in[1];  // (C, 8) i32
    const int*   cdown = (const int*)  d_in[2];  // (C, 8) i32
    float*       out   = (float*)d_out;          // (B, C) f32

    const int B = in_sizes[0] / (NELEC_ * NMO_);
    const int C = in_sizes[1] / NB_UP;

    slater_det_kernel<<<B, 2 * NCONF_>>>(mo, cup, cdown, out, C);
}

// round 5
// speedup vs baseline: 2.0445x; 2.0445x over previous
#include <cuda_runtime.h>

#define FULLMASK 0xffffffffu
#define NMO_   40
#define ROWS_  16
#define STRIDE 41   // (9*i + col) mod 32 distinct for i=0..7 -> conflict-free row gather

// Warp-cooperative Slater determinants: 8 lanes = one 8x8 matrix, one row/lane.
// Block: 512 threads = 64 groups = 32 configs x 2 spins for one walker.
// Per-thread state is ~8 floats -> fully register-resident (no local spills,
// which bound all previous single-thread-per-matrix versions).
__global__ __launch_bounds__(512, 2)
void slater_det_kernel(const float* __restrict__ mo,
                       const int*   __restrict__ cup,
                       const int*   __restrict__ cdown,
                       float*       __restrict__ out,
                       int nconf)
{
    __shared__ float mo_sh[ROWS_ * STRIDE];  // 656 floats
    __shared__ float sh_det[64];

    const int b  = blockIdx.y;
    const int c0 = blockIdx.x * 32;
    const int t  = threadIdx.x;

    // Stage this walker's MO block (16 x 40) with stride-41 rows.
    {
        const float* src = mo + (size_t)b * (ROWS_ * NMO_);
        #pragma unroll
        for (int idx = t; idx < ROWS_ * NMO_; idx += 512)
            mo_sh[(idx / NMO_) * STRIDE + (idx % NMO_)] = src[idx];
    }
    __syncthreads();

    const int g    = t >> 3;          // group id 0..63
    const int lid8 = t & 7;           // lane in group = matrix row index
    const int s    = g >> 5;          // spin: groups 0..31 up, 32..63 down
    const int c    = c0 + (g & 31);   // CI configuration
    const unsigned gmask = 0xFFu << (((t >> 3) & 3) * 8);  // this group's ballot byte

    // Each lane loads one column index; coalesced 32b loads across the warp.
    const int* cw    = (s == 0) ? cup : cdown;
    const int  mycol = __ldg(&cw[c * 8 + lid8]);
    const int  rowbase = (s * 8 + lid8) * STRIDE;

    // Gather my matrix row: a[j] = mo[b, s*8+lid8, cols[j]]
    float a[8];
    #pragma unroll
    for (int j = 0; j < 8; ++j) {
        const int colj = __shfl_sync(FULLMASK, mycol, j, 8);
        a[j] = mo_sh[rowbase + colj];
    }

    // Warp-cooperative LU with partial pivoting. No row data ever moves:
    // "virtual position" v tracks where each lane's row logically sits;
    // each realized transposition flips the sign.
    float det = 1.0f;
    int   v   = lid8;

    #pragma unroll
    for (int k = 0; k < 8; ++k) {
        const float ak  = a[k];
        const float val = (v >= k) ? fabsf(ak) : -1.0f;   // inactive rows excluded

        // group max of val
        float m = val;
        m = fmaxf(m, __shfl_xor_sync(FULLMASK, m, 1, 8));
        m = fmaxf(m, __shfl_xor_sync(FULLMASK, m, 2, 8));
        m = fmaxf(m, __shfl_xor_sync(FULLMASK, m, 4, 8));

        // pivot lane = lowest lane attaining the max (inactive val=-1 < m)
        const unsigned bal = __ballot_sync(FULLMASK, val == m);
        const int p = __ffs(bal & gmask) - 1;             // global lane id

        const float prk = __shfl_sync(FULLMASK, ak, p, 8);
        const int   vp  = __shfl_sync(FULLMASK, v,  p, 8);

        det *= prk;
        det = (vp != k) ? -det : det;                     // transposition sign

        // virtual-position swap: pivot -> slot k; old holder of k -> vp
        const bool ispiv = ((p & 7) == lid8);
        if (ispiv) v = k; else if (v == k) v = vp;

        // eliminate column k on still-active rows (v > k after the swap)
        const float f    = ak * __frcp_rn(prk);
        const bool  elim = (v > k);
        #pragma unroll
        for (int j = k + 1; j < 8; ++j) {
            const float prj = __shfl_sync(FULLMASK, a[j], p, 8);
            const float nj  = fmaf(-f, prj, a[j]);
            a[j] = elim ? nj : a[j];
        }
    }

    if (lid8 == 0) sh_det[g] = det;
    __syncthreads();

    // Combine spins and store (coalesced 128B per block).
    if (t < 32)
        out[(size_t)b * nconf + c0 + t] = sh_det[t] * sh_det[32 + t];
}

extern "C" void kernel_launch(void* const* d_in, const int* in_sizes, int n_in,
                              void* d_out, int out_size)
{
    const float* mo    = (const float*)d_in[0];  // (B, 16, 40) f32
    const int*   cup   = (const int*)  d_in[1];  // (C, 8) i32
    const int*   cdown = (const int*)  d_in[2];  // (C, 8) i32
    float*       out   = (float*)d_out;          // (B, C) f32

    const int B = in_sizes[0] / (ROWS_ * NMO_);
    const int C = in_sizes[1] / 8;

    dim3 grid(C / 32, B);
    slater_det_kernel<<<grid, 512>>>(mo, cup, cdown, out, C);
}

// round 6
// speedup vs baseline: 3.0584x; 1.4959x over previous
#include <cuda_runtime.h>

#define FULLMASK 0xffffffffu
#define NMO_   40
#define ROWS_  16
#define STRIDE 41      // stride-41 rows -> decorrelated bank residues for gather
#define CPB    128     // configs per block (512 threads = 256 pairs = 128 cfg x 2 spins)

// 4-way register select, r runtime, via FSEL tree (no dynamic reg indexing).
__device__ __forceinline__ float sel4f(float x0, float x1, float x2, float x3, int r) {
    float lo = (r & 1) ? x1 : x0;
    float hi = (r & 1) ? x3 : x2;
    return (r & 2) ? hi : lo;
}
__device__ __forceinline__ int sel4i(int x0, int x1, int x2, int x3, int r) {
    int lo = (r & 1) ? x1 : x0;
    int hi = (r & 1) ? x3 : x2;
    return (r & 2) ? hi : lo;
}

// Pair-cooperative Slater determinants: 2 lanes per 8x8 matrix, 4 rows/lane.
// Amortizes every shuffle over 16 determinants per warp (vs 4 in the 8-lane
// version), cutting MIO pressure ~4x while staying register-resident.
__global__ __launch_bounds__(512, 2)
void slater_det_kernel(const float* __restrict__ mo,
                       const int*   __restrict__ cup,
                       const int*   __restrict__ cdown,
                       float*       __restrict__ out,
                       int nconf)
{
    __shared__ float mo_sh[ROWS_ * STRIDE];   // 656 floats
    __shared__ float sh_det[2 * CPB];

    const int b  = blockIdx.y;
    const int c0 = blockIdx.x * CPB;
    const int t  = threadIdx.x;

    // Stage this walker's MO block (16 x 40) with stride-41 rows.
    {
        const float* src = mo + (size_t)b * (ROWS_ * NMO_);
        #pragma unroll
        for (int idx = t; idx < ROWS_ * NMO_; idx += 512)
            mo_sh[(idx / NMO_) * STRIDE + (idx % NMO_)] = src[idx];
    }
    __syncthreads();

    const int pairid = t >> 1;            // 0..255
    const int par    = t & 1;             // lane within pair
    const int s      = pairid >> 7;       // spin channel
    const int c      = c0 + (pairid & (CPB - 1));

    // Column indices: 8 ints = 2x int4 (both pair lanes load the same 32B).
    const int* cw = ((s == 0) ? cup : cdown) + c * 8;
    const int4 ci0 = __ldg((const int4*)cw);
    const int4 ci1 = __ldg((const int4*)cw + 1);
    const int cols[8] = {ci0.x, ci0.y, ci0.z, ci0.w, ci1.x, ci1.y, ci1.z, ci1.w};

    // Gather 4 rows of the 8x8 matrix: global row = s*8 + par*4 + r.
    float a[4][8];
    {
        const int rb = (s * 8 + par * 4) * STRIDE;
        #pragma unroll
        for (int r = 0; r < 4; ++r)
            #pragma unroll
            for (int j = 0; j < 8; ++j)
                a[r][j] = mo_sh[rb + r * STRIDE + cols[j]];
    }

    // LU with partial pivoting across the lane pair.
    // v[r] = virtual position of my local row r (rows never move).
    int v[4] = {par * 4 + 0, par * 4 + 1, par * 4 + 2, par * 4 + 3};
    float det = 1.0f;

    #pragma unroll
    for (int k = 0; k < 8; ++k) {
        // Pack |a[r][k]| with (row, parity) in the low 3 bits; inactive -> 0.
        // Unsigned max over 8 candidate keys = pivot (value + location).
        unsigned key = 0u;
        #pragma unroll
        for (int r = 0; r < 4; ++r) {
            unsigned kr = (__float_as_uint(fabsf(a[r][k])) & 0xFFFFFFF8u)
                          | (unsigned)(r << 1) | (unsigned)par;
            kr = (v[r] >= k) ? kr : 0u;
            key = (kr > key) ? kr : key;
        }
        {
            const unsigned ok = __shfl_xor_sync(FULLMASK, key, 1);
            key = (ok > key) ? ok : key;
        }
        const int wpar   = (int)(key & 1u);        // winning lane parity
        const int r_star = (int)((key >> 1) & 3u); // winning local row

        // Pivot value and its virtual position from the winning lane.
        const float candp = sel4f(a[0][k], a[1][k], a[2][k], a[3][k], r_star);
        const int   candv = sel4i(v[0], v[1], v[2], v[3], r_star);
        const float prk = __shfl_sync(FULLMASK, candp, wpar, 2);
        const int   vp  = __shfl_sync(FULLMASK, candv, wpar, 2);

        det *= prk;
        det = (vp != k) ? -det : det;              // transposition sign

        // Virtual swap: pivot row -> slot k; old holder of slot k -> vp.
        const bool meWin = (par == wpar);
        #pragma unroll
        for (int r = 0; r < 4; ++r)
            v[r] = (meWin && r == r_star) ? k : ((v[r] == k) ? vp : v[r]);

        // Unconditional elimination on ALL rows: frozen/pivot rows get
        // corrupted but are never read again (v-mask excludes them).
        const float inv = __frcp_rn(prk);
        float f[4];
        #pragma unroll
        for (int r = 0; r < 4; ++r) f[r] = a[r][k] * inv;

        #pragma unroll
        for (int j = k + 1; j < 8; ++j) {
            const float cj  = sel4f(a[0][j], a[1][j], a[2][j], a[3][j], r_star);
            const float prj = __shfl_sync(FULLMASK, cj, wpar, 2);
            #pragma unroll
            for (int r = 0; r < 4; ++r)
                a[r][j] = fmaf(-f[r], prj, a[r][j]);
        }
    }

    if (par == 0) sh_det[pairid] = det;
    __syncthreads();

    // Combine spins; coalesced 512B store per block.
    if (t < CPB)
        out[(size_t)b * nconf + c0 + t] = sh_det[t] * sh_det[CPB + t];
}

extern "C" void kernel_launch(void* const* d_in, const int* in_sizes, int n_in,
                              void* d_out, int out_size)
{
    const float* mo    = (const float*)d_in[0];  // (B, 16, 40) f32
    const int*   cup   = (const int*)  d_in[1];  // (C, 8) i32
    const int*   cdown = (const int*)  d_in[2];  // (C, 8) i32
    float*       out   = (float*)d_out;          // (B, C) f32

    const int B = in_sizes[0] / (ROWS_ * NMO_);
    const int C = in_sizes[1] / 8;

    dim3 grid(C / CPB, B);
    slater_det_kernel<<<grid, 512>>>(mo, cup, cdown, out, C);
}